// round 3
// baseline (speedup 1.0000x reference)
#include <cuda_runtime.h>
#include <cuda_bf16.h>

#define HD    1024
#define SLEN  256
#define TLEN  256
#define VOUT  32000
#define G4    4096
#define NCTA_REC 128
#define STEPS 512

// ---------------- device scratch ----------------
__device__ __nv_bfloat16 g_linw_bf[(size_t)VOUT * HD];   // 65.5 MB
__device__ __nv_bfloat16 g_wih_bf[2ul * G4 * HD];        // 16.8 MB
__device__ __nv_bfloat16 g_xbf[(size_t)STEPS * HD];      // 1 MB
__device__ float         g_G[2ul * SLEN * G4];           // 8 MB
__device__ __nv_bfloat16 g_Hbf[(size_t)TLEN * HD];       // 0.5 MB
__device__ float         g_hbuf[2][HD];
// per-CTA, per-step ready flags: one 32B sector per (step, cta) -> no L2-ALU serialization
__device__ unsigned      g_flag[(size_t)(STEPS + 1) * NCTA_REC * 8];

// ---------------- helpers ----------------
__device__ __forceinline__ void ffma2(unsigned long long &d,
                                      unsigned long long a, unsigned long long b) {
    asm("fma.rn.f32x2 %0, %1, %2, %0;" : "+l"(d) : "l"(a), "l"(b));
}
__device__ __forceinline__ void unpack2(unsigned long long v, float &lo, float &hi) {
    unsigned l, h;
    asm("mov.b64 {%0, %1}, %2;" : "=r"(l), "=r"(h) : "l"(v));
    lo = __uint_as_float(l); hi = __uint_as_float(h);
}
__device__ __forceinline__ unsigned ld_acq(const unsigned* p) {
    unsigned v;
    asm volatile("ld.acquire.gpu.global.u32 %0, [%1];" : "=r"(v) : "l"(p) : "memory");
    return v;
}
__device__ __forceinline__ void st_rel(unsigned* p, unsigned v) {
    asm volatile("st.release.gpu.global.u32 [%0], %1;" :: "l"(p), "r"(v) : "memory");
}
__device__ __forceinline__ float tanh_hw(float x) {
    float y;
    asm("tanh.approx.f32 %0, %1;" : "=f"(y) : "f"(x));
    return y;
}
__device__ __forceinline__ float sig_hw(float x) {
    return fmaf(tanh_hw(0.5f * x), 0.5f, 0.5f);
}
__device__ __forceinline__ void mma_bf16(float c[4],
                                         unsigned a0, unsigned a1, unsigned a2, unsigned a3,
                                         unsigned b0, unsigned b1) {
    asm volatile("mma.sync.aligned.m16n8k16.row.col.f32.bf16.bf16.f32 "
                 "{%0,%1,%2,%3}, {%4,%5,%6,%7}, {%8,%9}, {%0,%1,%2,%3};"
                 : "+f"(c[0]), "+f"(c[1]), "+f"(c[2]), "+f"(c[3])
                 : "r"(a0), "r"(a1), "r"(a2), "r"(a3), "r"(b0), "r"(b1));
}

// ---------------- 1) embedding gather (f32 -> bf16) ----------------
__global__ void embed_kernel(const int* __restrict__ src, const int* __restrict__ trg,
                             const int* __restrict__ start,
                             const float* __restrict__ enc_emb,
                             const float* __restrict__ dec_emb) {
    const int t = blockIdx.x;           // 0..511
    const int tid = threadIdx.x;        // 256
    const float* emb; int tok;
    if (t < SLEN) { tok = src[t]; emb = enc_emb; }
    else {
        int tt = t - SLEN;
        tok = (tt == 0) ? start[0] : trg[tt - 1];
        emb = dec_emb;
    }
    const float4 v = ((const float4*)(emb + (size_t)tok * HD))[tid];
    __nv_bfloat162 p0 = __floats2bfloat162_rn(v.x, v.y);
    __nv_bfloat162 p1 = __floats2bfloat162_rn(v.z, v.w);
    __nv_bfloat162* d = (__nv_bfloat162*)(g_xbf + (size_t)t * HD);
    d[2 * tid]     = p0;
    d[2 * tid + 1] = p1;
}

// ---------------- 2) f32 -> bf16 weight conversion + flag reset ----------------
__global__ void convert_kernel(const float* __restrict__ encWih,
                               const float* __restrict__ decWih,
                               const float* __restrict__ linW) {
    size_t i = (size_t)blockIdx.x * blockDim.x + threadIdx.x;
    size_t stride = (size_t)gridDim.x * blockDim.x;
    const size_t NF = (size_t)(STEPS + 1) * NCTA_REC * 8;
    for (size_t j = i; j < NF; j += stride) g_flag[j] = 0u;   // re-arm every launch/replay
    const size_t NW = (size_t)G4 * HD;
    for (size_t j = i; j < NW; j += stride) {
        g_wih_bf[j]      = __float2bfloat16(encWih[j]);
        g_wih_bf[NW + j] = __float2bfloat16(decWih[j]);
    }
    const size_t NL = (size_t)VOUT * HD;
    for (size_t j = i; j < NL; j += stride) g_linw_bf[j] = __float2bfloat16(linW[j]);
}

// ---------------- 3) G = X @ Wih^T + (bih+bhh), tensor cores ----------------
__global__ void __launch_bounds__(128) wx_mma(const float* __restrict__ eb_ih,
                                              const float* __restrict__ eb_hh,
                                              const float* __restrict__ db_ih,
                                              const float* __restrict__ db_hh) {
    const int net = blockIdx.z;
    const __nv_bfloat16* A = g_wih_bf + (size_t)net * G4 * HD;
    const __nv_bfloat16* B = g_xbf + (size_t)net * SLEN * HD;
    const float* bih = net ? db_ih : eb_ih;
    const float* bhh = net ? db_hh : eb_hh;
    float* Gout = g_G + (size_t)net * SLEN * G4;

    const int tid = threadIdx.x;
    const int w = tid >> 5, lane = tid & 31;
    const int group = lane >> 2, tig = lane & 3;
    const int bm = blockIdx.x * 128 + w * 32;
    const int bn = blockIdx.y * 64;

    float acc[2][8][4];
    #pragma unroll
    for (int mf = 0; mf < 2; mf++)
        #pragma unroll
        for (int nf = 0; nf < 8; nf++)
            #pragma unroll
            for (int q = 0; q < 4; q++) acc[mf][nf][q] = 0.f;

    for (int k0 = 0; k0 < HD; k0 += 16) {
        unsigned a[2][4], b[8][2];
        #pragma unroll
        for (int mf = 0; mf < 2; mf++) {
            const __nv_bfloat16* ab = A + (size_t)(bm + mf * 16 + group) * HD + k0 + 2 * tig;
            a[mf][0] = *(const unsigned*)(ab);
            a[mf][1] = *(const unsigned*)(ab + 8 * HD);
            a[mf][2] = *(const unsigned*)(ab + 8);
            a[mf][3] = *(const unsigned*)(ab + 8 * HD + 8);
        }
        #pragma unroll
        for (int nf = 0; nf < 8; nf++) {
            const __nv_bfloat16* bb = B + (size_t)(bn + nf * 8 + group) * HD + k0 + 2 * tig;
            b[nf][0] = *(const unsigned*)(bb);
            b[nf][1] = *(const unsigned*)(bb + 8);
        }
        #pragma unroll
        for (int mf = 0; mf < 2; mf++)
            #pragma unroll
            for (int nf = 0; nf < 8; nf++)
                mma_bf16(acc[mf][nf], a[mf][0], a[mf][1], a[mf][2], a[mf][3],
                         b[nf][0], b[nf][1]);
    }
    #pragma unroll
    for (int mf = 0; mf < 2; mf++) {
        const int m0 = bm + mf * 16 + group;
        const float bias0 = bih[m0] + bhh[m0];
        const float bias8 = bih[m0 + 8] + bhh[m0 + 8];
        #pragma unroll
        for (int nf = 0; nf < 8; nf++) {
            const int n = bn + nf * 8 + 2 * tig;
            Gout[(size_t)n * G4 + m0]           = acc[mf][nf][0] + bias0;
            Gout[(size_t)(n + 1) * G4 + m0]     = acc[mf][nf][1] + bias0;
            Gout[(size_t)n * G4 + m0 + 8]       = acc[mf][nf][2] + bias8;
            Gout[(size_t)(n + 1) * G4 + m0 + 8] = acc[mf][nf][3] + bias8;
        }
    }
}

// ---------------- 4) persistent LSTM recurrence ----------------
__device__ __forceinline__ void load_w(ulonglong2 (&wv)[4][8], const float* __restrict__ W,
                                       int w, int lane, int base) {
    #pragma unroll
    for (int j = 0; j < 4; j++) {
        const int r = w * 4 + j, q = r >> 3, u = r & 7;
        const float* row = W + (size_t)(q * HD + base + u) * HD + lane * 4;
        #pragma unroll
        for (int c = 0; c < 8; c++)
            wv[j][c] = *(const ulonglong2*)(row + c * 128);
    }
}

__global__ void __launch_bounds__(256, 1) rec_kernel(const float* __restrict__ encWhh,
                                                     const float* __restrict__ decWhh) {
    extern __shared__ float sm[];
    float* gsl    = sm;                 // [512][32] precomputed Wx+bias gates
    float* h_s    = gsl + STEPS * 32;   // [1024]
    float* gate_s = h_s + HD;           // [32]
    float* c_s    = gate_s + 32;        // [8]

    const int tid = threadIdx.x, cta = blockIdx.x;
    const int w = tid >> 5, lane = tid & 31;
    const int base = cta * 8;

    // preload this CTA's G slice for all 512 steps (64 KB)
    for (int i = tid; i < STEPS * 32; i += 256) {
        const int s = i >> 5, r = i & 31, q = r >> 3, u = r & 7;
        gsl[i] = g_G[(size_t)(s >> 8) * SLEN * G4 + (size_t)(s & 255) * G4 + q * HD + base + u];
    }

    // encoder Whh slice -> registers (f32, 128 regs)
    ulonglong2 wv[4][8];
    load_w(wv, encWhh, w, lane, base);

    if (tid < 8) {
        c_s[tid] = 0.f;
        g_hbuf[0][base + tid] = 0.f;
        __syncwarp(0xff);
        if (tid == 0) st_rel(&g_flag[(size_t)cta * 8], 1u);
    }
    __syncthreads();    // gsl + c_s ready

    for (int t = 0; t < STEPS; t++) {
        if (t == SLEN) load_w(wv, decWhh, w, lane, base);   // phase switch

        // ---- wait for all 128 CTAs to have published h(t): parallel flag poll ----
        for (;;) {
            unsigned f = 1u;
            if (tid < NCTA_REC)
                f = ld_acq(&g_flag[((size_t)t * NCTA_REC + tid) * 8]);
            if (__syncthreads_and(f != 0u)) break;
        }

        ((float4*)h_s)[tid] = ((const float4*)g_hbuf[t & 1])[tid];
        __syncthreads();

        // ---- Whh @ h for this CTA's 32 gate rows (packed f32x2 FMA) ----
        unsigned long long acc2[4] = {0ull, 0ull, 0ull, 0ull};
        #pragma unroll
        for (int c = 0; c < 8; c++) {
            const ulonglong2 hv = *(const ulonglong2*)(h_s + lane * 4 + c * 128);
            #pragma unroll
            for (int j = 0; j < 4; j++) {
                ffma2(acc2[j], wv[j][c].x, hv.x);
                ffma2(acc2[j], wv[j][c].y, hv.y);
            }
        }
        float accf[4];
        #pragma unroll
        for (int j = 0; j < 4; j++) {
            float lo, hi; unpack2(acc2[j], lo, hi);
            accf[j] = lo + hi;
        }
        #pragma unroll
        for (int off = 16; off; off >>= 1) {
            #pragma unroll
            for (int j = 0; j < 4; j++)
                accf[j] += __shfl_xor_sync(0xffffffffu, accf[j], off);
        }
        if (lane < 4) gate_s[w * 4 + lane] = accf[lane];
        __syncthreads();

        // ---- LSTM cell: 32 lanes = 4 gates x 8 units, HW tanh ----
        if (tid < 32) {
            const int q = tid >> 3, u = tid & 7;
            const float val = gate_s[tid] + gsl[t * 32 + tid];
            const float act = (q == 2) ? tanh_hw(val) : sig_hw(val);
            const float iv = __shfl_sync(0xffffffffu, act, u);
            const float fv = __shfl_sync(0xffffffffu, act, u + 8);
            const float gv = __shfl_sync(0xffffffffu, act, u + 16);
            const float ov = __shfl_sync(0xffffffffu, act, u + 24);
            if (tid < 8) {
                const float cc = fv * c_s[u] + iv * gv;
                c_s[u] = cc;
                const float hh = ov * tanh_hw(cc);
                g_hbuf[(t + 1) & 1][base + u] = hh;
                if (t >= SLEN) g_Hbf[(size_t)(t - SLEN) * HD + base + u] = __float2bfloat16(hh);
            }
            __syncwarp();
            if (tid == 0)
                st_rel(&g_flag[((size_t)(t + 1) * NCTA_REC + cta) * 8], 1u);
        }
        // next iteration's poll loop re-aligns all warps before h_s/gate_s reuse
    }
}

// ---------------- 5) logits = H @ linW^T + lin_b, tensor cores ----------------
__global__ void __launch_bounds__(128) logits_mma(const float* __restrict__ lin_b,
                                                  float* __restrict__ out) {
    const int tid = threadIdx.x;
    const int w = tid >> 5, lane = tid & 31;
    const int group = lane >> 2, tig = lane & 3;
    const size_t bm = (size_t)blockIdx.x * 128 + w * 32;
    const int bn = blockIdx.y * 64;

    float acc[2][8][4];
    #pragma unroll
    for (int mf = 0; mf < 2; mf++)
        #pragma unroll
        for (int nf = 0; nf < 8; nf++)
            #pragma unroll
            for (int q = 0; q < 4; q++) acc[mf][nf][q] = 0.f;

    for (int k0 = 0; k0 < HD; k0 += 16) {
        unsigned a[2][4], b[8][2];
        #pragma unroll
        for (int mf = 0; mf < 2; mf++) {
            const __nv_bfloat16* ab = g_linw_bf + (bm + mf * 16 + group) * HD + k0 + 2 * tig;
            a[mf][0] = *(const unsigned*)(ab);
            a[mf][1] = *(const unsigned*)(ab + 8 * HD);
            a[mf][2] = *(const unsigned*)(ab + 8);
            a[mf][3] = *(const unsigned*)(ab + 8 * HD + 8);
        }
        #pragma unroll
        for (int nf = 0; nf < 8; nf++) {
            const __nv_bfloat16* bb = g_Hbf + (size_t)(bn + nf * 8 + group) * HD + k0 + 2 * tig;
            b[nf][0] = *(const unsigned*)(bb);
            b[nf][1] = *(const unsigned*)(bb + 8);
        }
        #pragma unroll
        for (int mf = 0; mf < 2; mf++)
            #pragma unroll
            for (int nf = 0; nf < 8; nf++)
                mma_bf16(acc[mf][nf], a[mf][0], a[mf][1], a[mf][2], a[mf][3],
                         b[nf][0], b[nf][1]);
    }
    #pragma unroll
    for (int mf = 0; mf < 2; mf++) {
        const size_t m0 = bm + mf * 16 + group;
        const float bias0 = lin_b[m0];
        const float bias8 = lin_b[m0 + 8];
        #pragma unroll
        for (int nf = 0; nf < 8; nf++) {
            const int n = bn + nf * 8 + 2 * tig;
            out[(size_t)n * VOUT + m0]           = acc[mf][nf][0] + bias0;
            out[(size_t)(n + 1) * VOUT + m0]     = acc[mf][nf][1] + bias0;
            out[(size_t)n * VOUT + m0 + 8]       = acc[mf][nf][2] + bias8;
            out[(size_t)(n + 1) * VOUT + m0 + 8] = acc[mf][nf][3] + bias8;
        }
    }
}

// ---------------- 6) in-place row log_softmax (online 2-pass) ----------------
__global__ void __launch_bounds__(256) logsoftmax_kernel(float* __restrict__ out) {
    const int t = blockIdx.x;
    float* row = out + (size_t)t * VOUT;
    const int tid = threadIdx.x;
    __shared__ float smx[8], ssm[8];
    __shared__ float sbcast;

    float m = -3.4e38f, s = 0.f;
    for (int i = tid; i < VOUT; i += 256) {
        const float v = row[i];
        const float nm = fmaxf(m, v);
        s = s * __expf(m - nm) + __expf(v - nm);
        m = nm;
    }
    #pragma unroll
    for (int o = 16; o; o >>= 1) {
        const float mo = __shfl_xor_sync(0xffffffffu, m, o);
        const float so = __shfl_xor_sync(0xffffffffu, s, o);
        const float nm = fmaxf(m, mo);
        s = s * __expf(m - nm) + so * __expf(mo - nm);
        m = nm;
    }
    if ((tid & 31) == 0) { smx[tid >> 5] = m; ssm[tid >> 5] = s; }
    __syncthreads();
    if (tid == 0) {
        float M = smx[0], S = ssm[0];
        for (int wq = 1; wq < 8; wq++) {
            const float nm = fmaxf(M, smx[wq]);
            S = S * __expf(M - nm) + ssm[wq] * __expf(smx[wq] - nm);
            M = nm;
        }
        sbcast = M + logf(S);
    }
    __syncthreads();
    const float lse = sbcast;
    for (int i = tid; i < VOUT; i += 256) row[i] -= lse;
}

// ---------------- launch ----------------
extern "C" void kernel_launch(void* const* d_in, const int* in_sizes, int n_in,
                              void* d_out, int out_size) {
    const int*   src     = (const int*)d_in[0];
    const int*   trg     = (const int*)d_in[1];
    const int*   start   = (const int*)d_in[2];
    const float* enc_emb = (const float*)d_in[3];
    const float* enc_Wih = (const float*)d_in[4];
    const float* enc_Whh = (const float*)d_in[5];
    const float* enc_bih = (const float*)d_in[6];
    const float* enc_bhh = (const float*)d_in[7];
    const float* dec_emb = (const float*)d_in[8];
    const float* dec_Wih = (const float*)d_in[9];
    const float* dec_Whh = (const float*)d_in[10];
    const float* dec_bih = (const float*)d_in[11];
    const float* dec_bhh = (const float*)d_in[12];
    const float* lin_W   = (const float*)d_in[13];
    const float* lin_b   = (const float*)d_in[14];
    float* out = (float*)d_out;

    embed_kernel<<<STEPS, 256>>>(src, trg, start, enc_emb, dec_emb);
    convert_kernel<<<2048, 256>>>(enc_Wih, dec_Wih, lin_W);

    dim3 gwx(G4 / 128, SLEN / 64, 2);
    wx_mma<<<gwx, 128>>>(enc_bih, enc_bhh, dec_bih, dec_bhh);

    const int REC_SMEM = (STEPS * 32 + HD + 32 + 8) * 4;   // ~69.8 KB
    cudaFuncSetAttribute(rec_kernel, cudaFuncAttributeMaxDynamicSharedMemorySize, REC_SMEM);
    rec_kernel<<<NCTA_REC, 256, REC_SMEM>>>(enc_Whh, dec_Whh);

    dim3 gl(VOUT / 128, TLEN / 64);
    logits_mma<<<gl, 128>>>(lin_b, out);

    logsoftmax_kernel<<<TLEN, 256>>>(out);
}